// round 4
// baseline (speedup 1.0000x reference)
#include <cuda_runtime.h>
#include <math.h>

#define Nx   256
#define BN   2048      // 8*256

// ---------------- scratch ----------------
__device__ float g_A [BN*128];   // h @ Wm1[0:128]
__device__ float g_Bm[BN*128];   // h @ Wm1[128:256]
__device__ float g_P [BN*128];   // h @ Wu_top
__device__ float g_as[BN];
__device__ float g_bs[BN];
__device__ float g_S [BN*128];   // sum_j w_ij * relu(pre_ij)
__device__ float g_c [BN];       // sum_j w_ij
__device__ float g_M [128*128];  // Wm2 @ Wu_bot
__device__ float g_vb[128];      // bm2 @ Wu_bot + bu

typedef unsigned long long u64;

__device__ __forceinline__ u64 dup2(float a) {
    u64 r; unsigned au = __float_as_uint(a);
    asm("mov.b64 %0, {%1, %1};" : "=l"(r) : "r"(au));
    return r;
}
__device__ __forceinline__ void fma2(u64& acc, u64 a, u64 b) {
    asm("fma.rn.f32x2 %0, %1, %2, %0;" : "+l"(acc) : "l"(a), "l"(b));
}
__device__ __forceinline__ float2 unpk(u64 v) {
    unsigned lo, hi;
    asm("mov.b64 {%0, %1}, %2;" : "=r"(lo), "=r"(hi) : "l"(v));
    return make_float2(__uint_as_float(lo), __uint_as_float(hi));
}

// =======================================================================
// Stage 1: ONE wave.  blocks 0..95: h@[Wm1t|Wm1b|Wut] (64x128 tiles)
//          96,97: Wm2@Wu_bot   98..105: dots   106: vb
// grid 107, block 512, dyn smem = (128*68 + 128*136)*4 = 104448
// =======================================================================
#define S1_SMEM ((128*68 + 128*136) * 4)

__global__ void __launch_bounds__(512) k_stage1(
    const float* __restrict__ h,   const float* __restrict__ Wm1,
    const float* __restrict__ Wa,  const float* __restrict__ Wm2,
    const float* __restrict__ bm2, const float* __restrict__ Wu,
    const float* __restrict__ bu)
{
    extern __shared__ float sm[];
    const int bid = blockIdx.x;
    const int t   = threadIdx.x;

    if (bid < 98) {
        float* At = sm;              // [128][68]  k-major transposed A
        float* Ws = sm + 128*68;     // [128][136] k-major W
        const float *A, *W;
        float* dst;
        if (bid < 96) {
            int mt = bid / 3, nt = bid - mt*3;
            A = h + mt*64*128;
            W   = (nt == 0) ? Wm1 : (nt == 1) ? (Wm1 + 128*128) : Wu;
            dst = ((nt == 0) ? g_A : (nt == 1) ? g_Bm : g_P) + mt*64*128;
        } else {
            A = Wm2 + (bid - 96)*64*128;
            W = Wu + 128*128;
            dst = g_M + (bid - 96)*64*128;
        }
        // A tile 64x128 -> transposed
#pragma unroll
        for (int n = 0; n < 4; n++) {
            int l = t + n*512;                 // 0..2047 quads
            int r = l >> 5, kq = (l & 31) * 4;
            float4 v = *(const float4*)&A[r*128 + kq];
            At[(kq+0)*68 + r] = v.x; At[(kq+1)*68 + r] = v.y;
            At[(kq+2)*68 + r] = v.z; At[(kq+3)*68 + r] = v.w;
        }
        // W tile 128x128
#pragma unroll
        for (int n = 0; n < 8; n++) {
            int l = t + n*512;                 // 0..4095 quads
            int wk = l >> 5, wn = (l & 31) * 4;
            *(float4*)&Ws[wk*136 + wn] = *(const float4*)&W[wk*128 + wn];
        }
        __syncthreads();

        const int ty = t >> 5, lane = t & 31;  // rows ty*4.., cols lane*4..
        u64 acc[4][2];
#pragma unroll
        for (int r = 0; r < 4; r++) { acc[r][0] = 0ull; acc[r][1] = 0ull; }

#pragma unroll 4
        for (int k = 0; k < 128; k++) {
            float4 a4 = *(const float4*)&At[k*68 + ty*4];
            ulonglong2 w2 = *(const ulonglong2*)&Ws[k*136 + lane*4];
            u64 aa;
            aa = dup2(a4.x); fma2(acc[0][0], aa, w2.x); fma2(acc[0][1], aa, w2.y);
            aa = dup2(a4.y); fma2(acc[1][0], aa, w2.x); fma2(acc[1][1], aa, w2.y);
            aa = dup2(a4.z); fma2(acc[2][0], aa, w2.x); fma2(acc[2][1], aa, w2.y);
            aa = dup2(a4.w); fma2(acc[3][0], aa, w2.x); fma2(acc[3][1], aa, w2.y);
        }
#pragma unroll
        for (int r = 0; r < 4; r++) {
            float2 p = unpk(acc[r][0]), q = unpk(acc[r][1]);
            *(float4*)&dst[(ty*4 + r)*128 + lane*4] =
                make_float4(p.x, p.y, q.x, q.y);
        }

    } else if (bid < 106) {
        // dots: 256 rows per block, warp per 16 rows
        const int wrp = t >> 5, lane = t & 31;
        const int rowbase = (bid - 98) * 256 + wrp * 16;
        float4 wa1 = *(const float4*)&Wa[lane*4];
        float4 wa2 = *(const float4*)&Wa[128 + lane*4];
#pragma unroll 4
        for (int rr = 0; rr < 16; rr++) {
            int row = rowbase + rr;
            float4 hv = *(const float4*)&h[row*128 + lane*4];
            float sa = hv.x*wa1.x + hv.y*wa1.y + hv.z*wa1.z + hv.w*wa1.w;
            float sb = hv.x*wa2.x + hv.y*wa2.y + hv.z*wa2.z + hv.w*wa2.w;
#pragma unroll
            for (int o = 16; o; o >>= 1) {
                sa += __shfl_xor_sync(0xffffffffu, sa, o);
                sb += __shfl_xor_sync(0xffffffffu, sb, o);
            }
            if (lane == 0) { g_as[row] = sa; g_bs[row] = sb; }
        }
    } else {
        if (t < 128) {
            float acc = bu[t];
#pragma unroll 16
            for (int k = 0; k < 128; k++)
                acc = fmaf(bm2[k], Wu[(128 + k)*128 + t], acc);
            g_vb[t] = acc;
        }
    }
}

// =======================================================================
// k_pair: softmax + weighted relu aggregation -> g_S, g_c
// grid (16,8), block 512, dyn smem 205824
// =======================================================================
#define PAIR_SMEM ((32768 + 16384 + 2048 + 256) * 4)

__global__ void __launch_bounds__(512, 1) k_pair(
    const float* __restrict__ dist, const int* __restrict__ adj,
    const float* __restrict__ Wm1,  const float* __restrict__ bm1,
    const float* __restrict__ Wa,   const float* __restrict__ ba)
{
    extern __shared__ float sm[];
    float*  Bsh  = sm;                       // 256*128
    float4* dwsh = (float4*)(sm + 32768);    // [16][256] {d,d,w,w}
    float*  Ash  = sm + 32768 + 16384;       // 16*128 (A + bm1)
    float*  bssh = Ash + 2048;               // 256

    const int t = threadIdx.x;
    const int b = blockIdx.y, i0 = blockIdx.x * 16;
    const int lane = t & 31, wrp = t >> 5;

    // ---- fills
    {
        const float4* src = (const float4*)(g_Bm + (long)b*Nx*128);
        float4* d4 = (float4*)Bsh;
#pragma unroll
        for (int k = 0; k < 16; k++) d4[t + k*512] = src[t + k*512];
    }
#pragma unroll
    for (int k = 0; k < 4; k++) {
        int idx = t + k*512;
        Ash[idx] = g_A[(long)(b*Nx + i0)*128 + idx] + bm1[idx & 127];
    }
    if (t < 256) bssh[t] = g_bs[b*Nx + t];
    __syncthreads();

    // ---- phase 1: warp wrp -> i = i0 + wrp
    const float wa_d = Wa[256];
    {
        const int ig = b*Nx + i0 + wrp;
        const float a_i = g_as[ig] + ba[0];
        float l[8], dv[8]; int mk[8];
#pragma unroll
        for (int jj = 0; jj < 8; jj++) {
            int j = jj*32 + lane;
            float d = dist[(long)ig*Nx + j];
            int   m = adj [(long)ig*Nx + j];
            float x = fmaf(d, wa_d, a_i + bssh[j]);
            x = (x >= 0.f) ? x : 0.2f * x;
            l[jj] = m ? x : -1e9f;
            dv[jj] = d; mk[jj] = m;
        }
        float mx = l[0];
#pragma unroll
        for (int jj = 1; jj < 8; jj++) mx = fmaxf(mx, l[jj]);
#pragma unroll
        for (int o = 16; o; o >>= 1) mx = fmaxf(mx, __shfl_xor_sync(0xffffffffu, mx, o));
        float sum = 0.f, cs = 0.f;
#pragma unroll
        for (int jj = 0; jj < 8; jj++) {
            float e = expf(l[jj] - mx);
            l[jj] = e; sum += e;
            cs += mk[jj] ? e : 0.f;
        }
#pragma unroll
        for (int o = 16; o; o >>= 1) {
            sum += __shfl_xor_sync(0xffffffffu, sum, o);
            cs  += __shfl_xor_sync(0xffffffffu, cs,  o);
        }
        float inv = 1.f / sum;
#pragma unroll
        for (int jj = 0; jj < 8; jj++) {
            int j = jj*32 + lane;
            float w = mk[jj] ? l[jj]*inv : 0.f;
            dwsh[wrp*256 + j] = make_float4(dv[jj], dv[jj], w, w);
        }
        if (lane == 0) g_c[ig] = cs * inv;
    }

    // ---- phase 2 registers
    const int cp = t & 63, q = t >> 6;
    u64 a2[16], acc2[16];
#pragma unroll
    for (int i = 0; i < 16; i++) {
        a2[i]   = *(const u64*)&Ash[i*128 + cp*2];
        acc2[i] = 0ull;
    }
    const u64 wd2 = *(const u64*)&Wm1[256*128 + cp*2];
    __syncthreads();

    // ---- phase 2 (dw loads batched 8-at-a-time for latency hiding)
    const ulonglong2* dwp = (const ulonglong2*)dwsh;
#pragma unroll 1
    for (int jj = 0; jj < 32; jj++) {
        int j = jj*8 + q;
        u64 b2 = *(const u64*)&Bsh[j*128 + cp*2];
        ulonglong2 dw[8];
#pragma unroll
        for (int g = 0; g < 2; g++) {
#pragma unroll
            for (int i = 0; i < 8; i++) dw[i] = dwp[(g*8 + i)*256 + j];
#pragma unroll
            for (int i = 0; i < 8; i++) {
                asm("{\n\t"
                    ".reg .b64 tt;\n\t"
                    ".reg .f32 lo, hi;\n\t"
                    "add.rn.f32x2 tt, %1, %2;\n\t"
                    "fma.rn.f32x2 tt, %3, %4, tt;\n\t"
                    "mov.b64 {lo, hi}, tt;\n\t"
                    "max.f32 lo, lo, 0f00000000;\n\t"
                    "max.f32 hi, hi, 0f00000000;\n\t"
                    "mov.b64 tt, {lo, hi};\n\t"
                    "fma.rn.f32x2 %0, %5, tt, %0;\n\t"
                    "}"
                    : "+l"(acc2[g*8 + i])
                    : "l"(a2[g*8 + i]), "l"(b2), "l"(dw[i].x),
                      "l"(wd2), "l"(dw[i].y));
            }
        }
    }
    __syncthreads();   // done reading Bsh & dwsh

    // ---- reduce over q via smem overlay on dwsh
    u64* part = (u64*)dwsh;   // [16][8][64]
#pragma unroll
    for (int i = 0; i < 16; i++) part[(i*8 + q)*64 + cp] = acc2[i];
    __syncthreads();
#pragma unroll
    for (int rep = 0; rep < 2; rep++) {
        int it = t + rep*512;
        int i = it >> 6, cpp = it & 63;
        float2 s = make_float2(0.f, 0.f);
#pragma unroll
        for (int qq = 0; qq < 8; qq++) {
            float2 v = unpk(part[(i*8 + qq)*64 + cpp]);
            s.x += v.x; s.y += v.y;
        }
        *(float2*)&g_S[(long)(b*Nx + i0 + i)*128 + cpp*2] = s;
    }
}

// =======================================================================
// k_out: out = relu( g_P + S@M + g_c*vb )
// grid 64, block 512, tile 32x128, micro 2x4, dyn smem (128*34+128*132)*4
// =======================================================================
#define KO_SMEM ((128*34 + 128*132) * 4)

__global__ void __launch_bounds__(512) k_out(float* __restrict__ out)
{
    extern __shared__ float sm[];
    float* St = sm;              // [128][34]  k-major transposed S
    float* Ms = sm + 128*34;     // [128][132] k-major M
    const int t = threadIdx.x;
    const int row0 = blockIdx.x * 32;

    // S tile 32x128 -> transposed
#pragma unroll
    for (int n = 0; n < 2; n++) {
        int l = t + n*512;               // 0..1023 quads
        int r = l >> 5, kq = (l & 31) * 4;
        float4 v = *(const float4*)&g_S[(row0 + r)*128 + kq];
        St[(kq+0)*34 + r] = v.x; St[(kq+1)*34 + r] = v.y;
        St[(kq+2)*34 + r] = v.z; St[(kq+3)*34 + r] = v.w;
    }
    // M tile 128x128
#pragma unroll
    for (int n = 0; n < 8; n++) {
        int l = t + n*512;
        int wk = l >> 5, wn = (l & 31) * 4;
        *(float4*)&Ms[wk*132 + wn] = *(const float4*)&g_M[wk*128 + wn];
    }
    __syncthreads();

    const int ty = t >> 5, lane = t & 31;   // rows ty*2.., cols lane*4..
    u64 acc[2][2];
    acc[0][0] = acc[0][1] = acc[1][0] = acc[1][1] = 0ull;

#pragma unroll 4
    for (int k = 0; k < 128; k++) {
        float2 a2 = *(const float2*)&St[k*34 + ty*2];
        ulonglong2 w2 = *(const ulonglong2*)&Ms[k*132 + lane*4];
        u64 aa;
        aa = dup2(a2.x); fma2(acc[0][0], aa, w2.x); fma2(acc[0][1], aa, w2.y);
        aa = dup2(a2.y); fma2(acc[1][0], aa, w2.x); fma2(acc[1][1], aa, w2.y);
    }

    float4 vb4 = *(const float4*)&g_vb[lane*4];
#pragma unroll
    for (int r = 0; r < 2; r++) {
        int row = row0 + ty*2 + r;
        float cr = g_c[row];
        float4 pv = *(const float4*)&g_P[(long)row*128 + lane*4];
        float2 p = unpk(acc[r][0]), q = unpk(acc[r][1]);
        float4 o;
        o.x = fmaxf(pv.x + fmaf(cr, vb4.x, p.x),  0.f);
        o.y = fmaxf(pv.y + fmaf(cr, vb4.y, p.y),  0.f);
        o.z = fmaxf(pv.z + fmaf(cr, vb4.z, q.x),  0.f);
        o.w = fmaxf(pv.w + fmaf(cr, vb4.w, q.y),  0.f);
        *(float4*)&out[(long)row*128 + lane*4] = o;
    }
}

// =======================================================================
extern "C" void kernel_launch(void* const* d_in, const int* in_sizes, int n_in,
                              void* d_out, int out_size)
{
    const float* h    = (const float*)d_in[0];
    const int*   adj  = (const int*)  d_in[1];
    const float* dist = (const float*)d_in[2];
    const float* Wm1  = (const float*)d_in[3];
    const float* bm1  = (const float*)d_in[4];
    const float* Wm2  = (const float*)d_in[5];
    const float* bm2  = (const float*)d_in[6];
    const float* Wa   = (const float*)d_in[7];
    const float* ba   = (const float*)d_in[8];
    const float* Wu   = (const float*)d_in[9];
    const float* bu   = (const float*)d_in[10];
    float* out = (float*)d_out;

    cudaFuncSetAttribute(k_stage1, cudaFuncAttributeMaxDynamicSharedMemorySize,
                         S1_SMEM);
    cudaFuncSetAttribute(k_pair, cudaFuncAttributeMaxDynamicSharedMemorySize,
                         PAIR_SMEM);
    cudaFuncSetAttribute(k_out, cudaFuncAttributeMaxDynamicSharedMemorySize,
                         KO_SMEM);

    k_stage1<<<107, 512, S1_SMEM>>>(h, Wm1, Wa, Wm2, bm2, Wu, bu);
    k_pair  <<<dim3(16, 8), 512, PAIR_SMEM>>>(dist, adj, Wm1, bm1, Wa, ba);
    k_out   <<<64, 512, KO_SMEM>>>(out);
}